// round 13
// baseline (speedup 1.0000x reference)
#include <cuda_runtime.h>
#include <cuda_fp16.h>
#include <cstdint>

#define DD 128
#define MAXN 50048
#define MAXB 512
#define MAXL 10

// ---------------- scratch (device globals; no allocation) ----------------
__device__ __align__(16) float g_agg[(size_t)MAXN * DD];
__device__ float g_deg[MAXN];
__device__ unsigned char g_flag[MAXN];
__device__ __align__(16) float g_item_e[(size_t)MAXB * MAXL * DD];
__device__ __align__(16) float g_user_e[(size_t)MAXB * DD];
__device__ __align__(16) float g_seq_emb[(size_t)MAXB * DD];
__device__ __align__(16) __half g_v2e_h[(size_t)MAXN * DD];
__device__ __align__(16) __half g_seq_hi[(size_t)MAXB * DD];
__device__ __align__(16) __half g_seq_lo[(size_t)MAXB * DD];

// ---------------- helpers ----------------
__device__ __forceinline__ float warpReduce(float v) {
    v += __shfl_down_sync(0xffffffffu, v, 16);
    v += __shfl_down_sync(0xffffffffu, v, 8);
    v += __shfl_down_sync(0xffffffffu, v, 4);
    v += __shfl_down_sync(0xffffffffu, v, 2);
    v += __shfl_down_sync(0xffffffffu, v, 1);
    return v;
}
__device__ __forceinline__ float blockReduce128(float v, float* buf) {
    int tid = threadIdx.x;
    __syncthreads();
    float w = warpReduce(v);
    if ((tid & 31) == 0) buf[tid >> 5] = w;
    __syncthreads();
    return buf[0] + buf[1] + buf[2] + buf[3];
}
__device__ __forceinline__ float sigmoidf_(float x) {
    return 1.0f / (1.0f + expf(-x));
}
__device__ __forceinline__ uint32_t smem_u32(const void* p) {
    uint32_t a;
    asm("{ .reg .u64 t; cvta.to.shared.u64 t, %1; cvt.u32.u64 %0, t; }" : "=r"(a) : "l"(p));
    return a;
}

// ---------------- mma.sync / ldmatrix (baseline PTX, sm_80+) ----------------
__device__ __forceinline__ void ldsm_x4(uint32_t& r0, uint32_t& r1, uint32_t& r2,
                                        uint32_t& r3, uint32_t addr) {
    asm volatile("ldmatrix.sync.aligned.m8n8.x4.shared.b16 {%0,%1,%2,%3}, [%4];"
                 : "=r"(r0), "=r"(r1), "=r"(r2), "=r"(r3) : "r"(addr));
}
__device__ __forceinline__ void mma16816(float* c, uint32_t a0, uint32_t a1,
                                         uint32_t a2, uint32_t a3,
                                         uint32_t b0, uint32_t b1) {
    asm volatile(
        "mma.sync.aligned.m16n8k16.row.col.f32.f16.f16.f32 "
        "{%0,%1,%2,%3}, {%4,%5,%6,%7}, {%8,%9}, {%0,%1,%2,%3};"
        : "+f"(c[0]), "+f"(c[1]), "+f"(c[2]), "+f"(c[3])
        : "r"(a0), "r"(a1), "r"(a2), "r"(a3), "r"(b0), "r"(b1));
}

// ---------------- K0: zero deg/flag ----------------
__global__ void k_zero(int N) {
    int gid = blockIdx.x * blockDim.x + threadIdx.x;
    int stride = gridDim.x * blockDim.x;
    for (int i = gid; i < N; i += stride) { g_deg[i] = 0.f; g_flag[i] = 0; }
}

// ---------------- K1: flag needed nodes ----------------
__global__ void k_flags(const int* __restrict__ seq, const int* __restrict__ user,
                        const int* __restrict__ item_num, int BS, int L) {
    int t = blockIdx.x * blockDim.x + threadIdx.x;
    int total = BS * L + BS;
    if (t >= total) return;
    if (t < BS * L) g_flag[seq[t]] = 1;
    else            g_flag[user[t - BS * L] + item_num[0]] = 1;
}

// ---------------- K1b: zero agg rows only where flagged ----------------
__global__ void k_zero_agg(int N) {
    int gw = (blockIdx.x * blockDim.x + threadIdx.x) >> 5;
    int lane = threadIdx.x & 31;
    if (gw >= N) return;
    if (g_flag[gw]) {
        float4 z = make_float4(0.f, 0.f, 0.f, 0.f);
        ((float4*)(g_agg + (size_t)gw * DD))[lane] = z;
    }
}

// ---------------- K2: fused flag-check + scatter (ballot + red.v4) --------
__global__ void k_scatter_fused(const int* __restrict__ edge_src,
                                const int* __restrict__ edge_dst,
                                const float* __restrict__ v2e, int E) {
    int lane = threadIdx.x & 31;
    int e = blockIdx.x * blockDim.x + threadIdx.x;
    bool p = false;
    int dst = 0;
    if (e < E) { dst = edge_dst[e]; p = (g_flag[dst] != 0); }
    unsigned m = __ballot_sync(0xffffffffu, p);
    while (m) {
        int src_lane = __ffs(m) - 1;
        m &= m - 1;
        int dd = __shfl_sync(0xffffffffu, dst, src_lane);
        int ee = __shfl_sync(0xffffffffu, e, src_lane);
        int src = edge_src[ee];                     // broadcast load
        float4 v = ((const float4*)(v2e + (size_t)src * DD))[lane];
        float* a = g_agg + (size_t)dd * DD + lane * 4;
        asm volatile("red.global.add.v4.f32 [%0], {%1, %2, %3, %4};"
                     :: "l"(a), "f"(v.x), "f"(v.y), "f"(v.z), "f"(v.w)
                     : "memory");
        if (lane == src_lane) atomicAdd(&g_deg[dd], 1.0f);
    }
}

// ---------------- K4: SAGE rows, 16 rows/block, MLP-friendly gathers ------
#define RG 16
__global__ void k_rows(const float* __restrict__ v2e, const float* __restrict__ W_self,
                       const float* __restrict__ W_neigh, const float* __restrict__ b_sage,
                       const int* __restrict__ seq, const int* __restrict__ user,
                       const int* __restrict__ item_num, int L, int totalRows) {
    __shared__ float sx[RG][DD], sn[RG][DD];
    __shared__ int s_idx[RG];
    int j = threadIdx.x;
    int base = blockIdx.x * RG;

    if (j < RG) {
        int r = base + j;
        int idx = 0;
        if (r < totalRows) {
            int b = r / (L + 1), s = r - b * (L + 1);
            idx = (s < L) ? seq[b * L + s] : (user[b] + item_num[0]);
        }
        s_idx[j] = idx;
    }
    __syncthreads();

    int idxr[RG];
#pragma unroll
    for (int g = 0; g < RG; g++) idxr[g] = s_idx[g];
#pragma unroll
    for (int g = 0; g < RG; g++) {
        int r = base + g;
        float x = 0.f, nr = 0.f, dg = 1.f;
        if (r < totalRows) {
            x  = v2e[(size_t)idxr[g] * DD + j];
            nr = g_agg[(size_t)idxr[g] * DD + j];
            dg = g_deg[idxr[g]];
        }
        sx[g][j] = x;
        sn[g][j] = nr / fmaxf(dg, 1.0f);
    }
    __syncthreads();

    float bj = b_sage[j];
    float acc[RG];
#pragma unroll
    for (int g = 0; g < RG; g++) acc[g] = bj;
#pragma unroll 4
    for (int k = 0; k < DD; k++) {
        float ws = W_self[k * DD + j];
        float wn = W_neigh[k * DD + j];
#pragma unroll
        for (int g = 0; g < RG; g++)
            acc[g] = fmaf(sx[g][k], ws, fmaf(sn[g][k], wn, acc[g]));
    }
#pragma unroll 1
    for (int g = 0; g < RG; g++) {
        int r = base + g;
        if (r >= totalRows) continue;
        int b = r / (L + 1), s = r - b * (L + 1);
        float* outp = (s < L) ? (g_item_e + ((size_t)(b * L + s)) * DD)
                              : (g_user_e + (size_t)b * DD);
        float h1 = fmaxf(acc[g], 0.f);
        outp[j] = (h1 + sx[g][j]) * 0.5f;
    }
}

// ---------------- K5: fused session attention (R8 form, untouched) --------
__global__ void k_attn(const float* __restrict__ pos_w, const float* __restrict__ w1,
                       const float* __restrict__ w2, const float* __restrict__ glu1_w,
                       const float* __restrict__ glu1_b, const float* __restrict__ glu2_w,
                       const float* __restrict__ w3, const float* __restrict__ w4,
                       const float* __restrict__ glu3_w, const float* __restrict__ glu3_b,
                       const float* __restrict__ glu4_w, const float* __restrict__ wc_w,
                       const float* __restrict__ wc_b, const int* __restrict__ mask,
                       const int* __restrict__ pos_idx, int L) {
    int b = blockIdx.x, j = threadIdx.x;
    __shared__ float s_item[MAXL * DD], s_aux[MAXL * DD];
    __shared__ float s_user[DD], s_hs[DD];
    __shared__ float s_m[MAXL], s_beta[MAXL], s_rbuf[4], s_alpha;

    for (int l = 0; l < L; l++)
        s_item[l * DD + j] = g_item_e[((size_t)(b * L + l)) * DD + j];
    for (int l = L; l < MAXL; l++) s_item[l * DD + j] = 0.f;
    s_user[j] = g_user_e[(size_t)b * DD + j];
    if (j < MAXL) s_m[j] = (j < L) ? (float)mask[b * L + j] : 0.f;
    for (int l = 0; l < L; l++)
        s_aux[l * DD + j] = pos_w[(size_t)pos_idx[b * L + l] * DD + j];
    for (int l = L; l < MAXL; l++) s_aux[l * DD + j] = 0.f;
    __syncthreads();

    float msum = 0.f;
    for (int l = 0; l < MAXL; l++) msum += s_m[l];
    float hsv = 0.f;
    for (int l = 0; l < MAXL; l++) hsv += s_item[l * DD + j] * s_m[l];
    hsv /= msum;
    s_hs[j] = hsv;
    __syncthreads();

    float acc[MAXL];
#pragma unroll
    for (int l = 0; l < MAXL; l++) acc[l] = 0.f;
#pragma unroll 8
    for (int k = 0; k < DD; k++) {
        float w = w1[k * DD + j];
#pragma unroll
        for (int l = 0; l < MAXL; l++) acc[l] = fmaf(s_aux[l * DD + k], w, acc[l]);
    }
#pragma unroll 8
    for (int k = 0; k < DD; k++) {
        float w = w1[(DD + k) * DD + j];
#pragma unroll
        for (int l = 0; l < MAXL; l++) acc[l] = fmaf(s_item[l * DD + k], w, acc[l]);
    }
    __syncthreads();
#pragma unroll
    for (int l = 0; l < MAXL; l++) s_aux[l * DD + j] = tanhf(acc[l]);
    __syncthreads();

    float hsg = 0.f;
#pragma unroll 8
    for (int k = 0; k < DD; k++) hsg = fmaf(s_hs[k], glu2_w[k * DD + j], hsg);
#pragma unroll
    for (int l = 0; l < MAXL; l++) acc[l] = 0.f;
#pragma unroll 8
    for (int k = 0; k < DD; k++) {
        float g = glu1_w[k * DD + j];
#pragma unroll
        for (int l = 0; l < MAXL; l++) acc[l] = fmaf(s_aux[l * DD + k], g, acc[l]);
    }
    float w2j = w2[j], g1b = glu1_b[j];
    for (int l = 0; l < MAXL; l++) {
        float g1 = sigmoidf_(acc[l] + g1b + hsg);
        float tot = blockReduce128(g1 * w2j, s_rbuf);
        if (j == 0) s_beta[l] = tot * s_m[l];
    }
    __syncthreads();
    float sv = 0.f;
    for (int l = 0; l < MAXL; l++) sv = fmaf(s_beta[l], s_item[l * DD + j], sv);

#pragma unroll
    for (int l = 0; l < MAXL; l++) acc[l] = 0.f;
#pragma unroll 8
    for (int k = 0; k < DD; k++) {
        float w = w3[k * DD + j];
#pragma unroll
        for (int l = 0; l < MAXL; l++) acc[l] = fmaf(s_item[l * DD + k], w, acc[l]);
    }
    __syncthreads();
#pragma unroll
    for (int l = 0; l < MAXL; l++) s_aux[l * DD + j] = tanhf(acc[l]);
    __syncthreads();

    float ueg = 0.f;
#pragma unroll 8
    for (int k = 0; k < DD; k++) ueg = fmaf(s_user[k], glu4_w[k * DD + j], ueg);
#pragma unroll
    for (int l = 0; l < MAXL; l++) acc[l] = 0.f;
#pragma unroll 8
    for (int k = 0; k < DD; k++) {
        float g = glu3_w[k * DD + j];
#pragma unroll
        for (int l = 0; l < MAXL; l++) acc[l] = fmaf(s_aux[l * DD + k], g, acc[l]);
    }
    float w4j = w4[j], g3b = glu3_b[j];
    for (int l = 0; l < MAXL; l++) {
        float g3 = sigmoidf_(acc[l] + g3b + ueg);
        float tot = blockReduce128(g3 * w4j, s_rbuf);
        if (j == 0) s_beta[l] = tot * s_m[l];
    }
    __syncthreads();
    float su = 0.f;
    for (int l = 0; l < MAXL; l++) su = fmaf(s_beta[l], s_item[l * DD + j], su);

    float pa = sv * wc_w[j] + su * wc_w[DD + j];
    float asum = blockReduce128(pa, s_rbuf);
    if (j == 0) s_alpha = sigmoidf_(asum + wc_b[0]);
    __syncthreads();
    float alpha = s_alpha;
    g_seq_emb[(size_t)b * DD + j] = s_user[j] + alpha * sv + (1.0f - alpha) * su;
}

// ---------------- K5b: fp16 conversions ----------------
__global__ void k_split_v2e(const float* __restrict__ src, int n4) {
    int i = blockIdx.x * blockDim.x + threadIdx.x;
    if (i >= n4) return;
    float4 v = ((const float4*)src)[i];
    __half2* H = (__half2*)g_v2e_h;
    H[i * 2]     = __floats2half2_rn(v.x, v.y);
    H[i * 2 + 1] = __floats2half2_rn(v.z, v.w);
}
__global__ void k_split_seq(int n4) {
    int i = blockIdx.x * blockDim.x + threadIdx.x;
    if (i >= n4) return;
    float4 v = ((const float4*)g_seq_emb)[i];
    __half h0 = __float2half_rn(v.x), h1 = __float2half_rn(v.y);
    __half h2 = __float2half_rn(v.z), h3 = __float2half_rn(v.w);
    __half l0 = __float2half_rn(v.x - __half2float(h0));
    __half l1 = __float2half_rn(v.y - __half2float(h1));
    __half l2 = __float2half_rn(v.z - __half2float(h2));
    __half l3 = __float2half_rn(v.w - __half2float(h3));
    __half2* H = (__half2*)g_seq_hi;
    __half2* Lp = (__half2*)g_seq_lo;
    __half2 a; a.x = h0; a.y = h1; H[i * 2] = a;
    a.x = h2; a.y = h3; H[i * 2 + 1] = a;
    a.x = l0; a.y = l1; Lp[i * 2] = a;
    a.x = l2; a.y = l3; Lp[i * 2 + 1] = a;
}

// ---------------- K6: HMMA fp16x2-split GEMM: out = seq_emb @ v2e[1:]^T ----
#define TM 128
#define TN 64
#define ASTR 136
#define ROWB (ASTR * 2)            // 272 bytes
#define ATILEB (128 * ROWB)        // 34816
#define BTILEB (64 * ROWB)         // 17408
#define SA_HI 0
#define SA_LO ATILEB
#define SB    (2 * ATILEB)
#define SM_TOT (2 * ATILEB + BTILEB)   // 87040

__global__ void __launch_bounds__(256, 2)
k_gemm_mma(float* __restrict__ out, int N, int Nout, int BS) {
    extern __shared__ char smem[];
    uint32_t sb = smem_u32(smem);
    int tid = threadIdx.x;
    int wid = tid >> 5, lane = tid & 31;
    int bn = blockIdx.x, bm = blockIdx.y;
    int rowBase = bm * TM;
    int colBase = bn * TN;

    {
        const uint4* aH = (const uint4*)g_seq_hi;
        const uint4* aL = (const uint4*)g_seq_lo;
        uint4 z = make_uint4(0, 0, 0, 0);
        for (int i = tid; i < 128 * 16; i += 256) {
            int r = i >> 4, c = i & 15;
            uint32_t dst = (uint32_t)(r * ROWB + c * 16);
            int ga = rowBase + r;
            uint4 vh = z, vl = z;
            if (ga < BS) { vh = aH[ga * 16 + c]; vl = aL[ga * 16 + c]; }
            *(uint4*)(smem + SA_HI + dst) = vh;
            *(uint4*)(smem + SA_LO + dst) = vl;
        }
        const uint4* bH = (const uint4*)g_v2e_h;
        for (int i = tid; i < 64 * 16; i += 256) {
            int r = i >> 4, c = i & 15;
            uint32_t dst = (uint32_t)(r * ROWB + c * 16);
            int gb = 1 + colBase + r;
            uint4 wh = z;
            if (gb < N) wh = bH[(size_t)gb * 16 + c];
            *(uint4*)(smem + SB + dst) = wh;
        }
    }
    __syncthreads();

    int warp_m = (wid >> 1) * 32;
    int warp_n = (wid & 1) * 32;

    int a_row = (lane & 7) + ((lane >> 3) & 1) * 8;
    int a_k8  = ((lane >> 4) & 1) * 8;
    int b_row = (lane & 7) + ((lane >> 4) & 1) * 8;
    int b_k8  = ((lane >> 3) & 1) * 8;

    float acc[2][4][4];
#pragma unroll
    for (int mi = 0; mi < 2; mi++)
#pragma unroll
        for (int nb = 0; nb < 4; nb++)
#pragma unroll
            for (int q = 0; q < 4; q++) acc[mi][nb][q] = 0.f;

#pragma unroll
    for (int ks = 0; ks < 8; ks++) {
        int kc = ks * 16;
        uint32_t bb[8];
        {
            uint32_t addr0 = sb + SB + (uint32_t)((warp_n + b_row) * ROWB +
                                                  (kc + b_k8) * 2);
            ldsm_x4(bb[0], bb[1], bb[2], bb[3], addr0);
            uint32_t addr1 = addr0 + 16 * ROWB;
            ldsm_x4(bb[4], bb[5], bb[6], bb[7], addr1);
        }
#pragma unroll
        for (int t = 0; t < 2; t++) {
            uint32_t aBase = sb + (t == 0 ? SA_HI : SA_LO);
#pragma unroll
            for (int mi = 0; mi < 2; mi++) {
                uint32_t a0, a1, a2, a3;
                uint32_t addr = aBase + (uint32_t)((warp_m + mi * 16 + a_row) * ROWB +
                                                   (kc + a_k8) * 2);
                ldsm_x4(a0, a1, a2, a3, addr);
                mma16816(acc[mi][0], a0, a1, a2, a3, bb[0], bb[1]);
                mma16816(acc[mi][1], a0, a1, a2, a3, bb[2], bb[3]);
                mma16816(acc[mi][2], a0, a1, a2, a3, bb[4], bb[5]);
                mma16816(acc[mi][3], a0, a1, a2, a3, bb[6], bb[7]);
            }
        }
    }

    int grp = lane >> 2;
    int lc2 = (lane & 3) * 2;
#pragma unroll
    for (int mi = 0; mi < 2; mi++) {
        int r0 = rowBase + warp_m + mi * 16 + grp;
        if (r0 >= BS) continue;
        size_t ro0 = (size_t)r0 * (size_t)Nout;
        size_t ro1 = (size_t)(r0 + 8) * (size_t)Nout;
#pragma unroll
        for (int nb = 0; nb < 4; nb++) {
            int col = colBase + warp_n + nb * 8 + lc2;
            if (col < Nout)     out[ro0 + col]     = acc[mi][nb][0];
            if (col + 1 < Nout) out[ro0 + col + 1] = acc[mi][nb][1];
            if (col < Nout)     out[ro1 + col]     = acc[mi][nb][2];
            if (col + 1 < Nout) out[ro1 + col + 1] = acc[mi][nb][3];
        }
    }
}

// ---------------- launch ----------------
extern "C" void kernel_launch(void* const* d_in, const int* in_sizes, int n_in,
                              void* d_out, int out_size) {
    const int* user     = (const int*)d_in[0];
    const int* seq      = (const int*)d_in[1];
    const int* mask     = (const int*)d_in[2];
    const int* pos_idx  = (const int*)d_in[4];
    const int* edge_src = (const int*)d_in[5];
    const int* edge_dst = (const int*)d_in[6];
    const int* item_num = (const int*)d_in[7];
    const float* v2e    = (const float*)d_in[8];
    const float* pos_w  = (const float*)d_in[9];
    const float* W_self = (const float*)d_in[10];
    const float* W_neigh= (const float*)d_in[11];
    const float* b_sage = (const float*)d_in[12];
    const float* w1     = (const float*)d_in[13];
    const float* w2     = (const float*)d_in[14];
    const float* glu1_w = (const float*)d_in[15];
    const float* glu1_b = (const float*)d_in[16];
    const float* glu2_w = (const float*)d_in[17];
    const float* w3     = (const float*)d_in[18];
    const float* w4     = (const float*)d_in[19];
    const float* glu3_w = (const float*)d_in[20];
    const float* glu3_b = (const float*)d_in[21];
    const float* glu4_w = (const float*)d_in[22];
    const float* wc_w   = (const float*)d_in[23];
    const float* wc_b   = (const float*)d_in[24];
    float* out = (float*)d_out;

    int BS = in_sizes[0];
    int L  = in_sizes[1] / BS;
    int E  = in_sizes[5];
    int N  = in_sizes[8] / DD;
    int Nout = N - 1;

    k_zero<<<256, 256>>>(N);                                          // idx 0
    int tot = BS * L + BS;
    k_flags<<<(tot + 255) / 256, 256>>>(seq, user, item_num, BS, L);  // idx 1
    k_zero_agg<<<(N * 32 + 255) / 256, 256>>>(N);                     // idx 2
    k_scatter_fused<<<(E + 255) / 256, 256>>>(edge_src, edge_dst, v2e, E); // idx 3 (profiled)
    k_split_v2e<<<(N * DD / 4 + 255) / 256, 256>>>(v2e, N * DD / 4);  // idx 4
    int totalRows = BS * (L + 1);
    k_rows<<<(totalRows + RG - 1) / RG, 128>>>(v2e, W_self, W_neigh, b_sage,
                                               seq, user, item_num, L, totalRows);
    k_attn<<<BS, 128>>>(pos_w, w1, w2, glu1_w, glu1_b, glu2_w, w3, w4,
                        glu3_w, glu3_b, glu4_w, wc_w, wc_b, mask, pos_idx, L);
    k_split_seq<<<(BS * DD / 4 + 255) / 256, 256>>>(BS * DD / 4);

    cudaFuncSetAttribute(k_gemm_mma, cudaFuncAttributeMaxDynamicSharedMemorySize, SM_TOT);
    dim3 grid((Nout + TN - 1) / TN, (BS + TM - 1) / TM);
    k_gemm_mma<<<grid, 256, SM_TOT>>>(out, N, Nout, BS);
}

// round 14
// speedup vs baseline: 1.2993x; 1.2993x over previous
#include <cuda_runtime.h>
#include <cuda_fp16.h>
#include <cstdint>

#define DD 128
#define MAXN 50048
#define MAXB 512
#define MAXL 10

// ---------------- scratch (device globals; no allocation) ----------------
__device__ __align__(16) float g_agg[(size_t)MAXN * DD];
__device__ float g_deg[MAXN];
__device__ unsigned char g_flag[MAXN];
__device__ __align__(16) float g_item_e[(size_t)MAXB * MAXL * DD];
__device__ __align__(16) float g_user_e[(size_t)MAXB * DD];
__device__ __align__(16) float g_seq_emb[(size_t)MAXB * DD];
__device__ __align__(16) __half g_v2e_h[(size_t)MAXN * DD];
__device__ __align__(16) __half g_seq_hi[(size_t)MAXB * DD];
__device__ __align__(16) __half g_seq_lo[(size_t)MAXB * DD];

// ---------------- helpers ----------------
__device__ __forceinline__ float warpReduce(float v) {
    v += __shfl_down_sync(0xffffffffu, v, 16);
    v += __shfl_down_sync(0xffffffffu, v, 8);
    v += __shfl_down_sync(0xffffffffu, v, 4);
    v += __shfl_down_sync(0xffffffffu, v, 2);
    v += __shfl_down_sync(0xffffffffu, v, 1);
    return v;
}
__device__ __forceinline__ float blockReduce128(float v, float* buf) {
    int tid = threadIdx.x;
    __syncthreads();
    float w = warpReduce(v);
    if ((tid & 31) == 0) buf[tid >> 5] = w;
    __syncthreads();
    return buf[0] + buf[1] + buf[2] + buf[3];
}
__device__ __forceinline__ float sigmoidf_(float x) {
    return 1.0f / (1.0f + expf(-x));
}
__device__ __forceinline__ uint32_t smem_u32(const void* p) {
    uint32_t a;
    asm("{ .reg .u64 t; cvta.to.shared.u64 t, %1; cvt.u32.u64 %0, t; }" : "=r"(a) : "l"(p));
    return a;
}

// ---------------- mma.sync / ldmatrix (baseline PTX, sm_80+) ----------------
__device__ __forceinline__ void ldsm_x4(uint32_t& r0, uint32_t& r1, uint32_t& r2,
                                        uint32_t& r3, uint32_t addr) {
    asm volatile("ldmatrix.sync.aligned.m8n8.x4.shared.b16 {%0,%1,%2,%3}, [%4];"
                 : "=r"(r0), "=r"(r1), "=r"(r2), "=r"(r3) : "r"(addr));
}
__device__ __forceinline__ void mma16816(float* c, uint32_t a0, uint32_t a1,
                                         uint32_t a2, uint32_t a3,
                                         uint32_t b0, uint32_t b1) {
    asm volatile(
        "mma.sync.aligned.m16n8k16.row.col.f32.f16.f16.f32 "
        "{%0,%1,%2,%3}, {%4,%5,%6,%7}, {%8,%9}, {%0,%1,%2,%3};"
        : "+f"(c[0]), "+f"(c[1]), "+f"(c[2]), "+f"(c[3])
        : "r"(a0), "r"(a1), "r"(a2), "r"(a3), "r"(b0), "r"(b1));
}

// ---------------- K0: zero deg/flag ----------------
__global__ void k_zero(int N) {
    int gid = blockIdx.x * blockDim.x + threadIdx.x;
    int stride = gridDim.x * blockDim.x;
    for (int i = gid; i < N; i += stride) { g_deg[i] = 0.f; g_flag[i] = 0; }
}

// ---------------- K1: flag needed nodes ----------------
__global__ void k_flags(const int* __restrict__ seq, const int* __restrict__ user,
                        const int* __restrict__ item_num, int BS, int L) {
    int t = blockIdx.x * blockDim.x + threadIdx.x;
    int total = BS * L + BS;
    if (t >= total) return;
    if (t < BS * L) g_flag[seq[t]] = 1;
    else            g_flag[user[t - BS * L] + item_num[0]] = 1;
}

// ---------------- K1b: zero agg rows only where flagged ----------------
__global__ void k_zero_agg(int N) {
    int gw = (blockIdx.x * blockDim.x + threadIdx.x) >> 5;
    int lane = threadIdx.x & 31;
    if (gw >= N) return;
    if (g_flag[gw]) {
        float4 z = make_float4(0.f, 0.f, 0.f, 0.f);
        ((float4*)(g_agg + (size_t)gw * DD))[lane] = z;
    }
}

// ---------------- K2: fused flag-check + scatter (ballot, scalar atomics) --
__global__ void k_scatter_fused(const int* __restrict__ edge_src,
                                const int* __restrict__ edge_dst,
                                const float* __restrict__ v2e, int E) {
    int lane = threadIdx.x & 31;
    int e = blockIdx.x * blockDim.x + threadIdx.x;
    bool p = false;
    int dst = 0;
    if (e < E) { dst = edge_dst[e]; p = (g_flag[dst] != 0); }
    unsigned m = __ballot_sync(0xffffffffu, p);
    while (m) {
        int src_lane = __ffs(m) - 1;
        m &= m - 1;
        int dd = __shfl_sync(0xffffffffu, dst, src_lane);
        int ee = __shfl_sync(0xffffffffu, e, src_lane);
        int src = edge_src[ee];                     // broadcast load
        float4 v = ((const float4*)(v2e + (size_t)src * DD))[lane];
        float* a = g_agg + (size_t)dd * DD + lane * 4;
        atomicAdd(a + 0, v.x);
        atomicAdd(a + 1, v.y);
        atomicAdd(a + 2, v.z);
        atomicAdd(a + 3, v.w);
        if (lane == src_lane) atomicAdd(&g_deg[dd], 1.0f);
    }
}

// ---------------- K4: SAGE rows, 16 rows/block, MLP-friendly gathers ------
#define RG 16
__global__ void k_rows(const float* __restrict__ v2e, const float* __restrict__ W_self,
                       const float* __restrict__ W_neigh, const float* __restrict__ b_sage,
                       const int* __restrict__ seq, const int* __restrict__ user,
                       const int* __restrict__ item_num, int L, int totalRows) {
    __shared__ float sx[RG][DD], sn[RG][DD];
    __shared__ int s_idx[RG];
    int j = threadIdx.x;
    int base = blockIdx.x * RG;

    if (j < RG) {
        int r = base + j;
        int idx = 0;
        if (r < totalRows) {
            int b = r / (L + 1), s = r - b * (L + 1);
            idx = (s < L) ? seq[b * L + s] : (user[b] + item_num[0]);
        }
        s_idx[j] = idx;
    }
    __syncthreads();

    int idxr[RG];
#pragma unroll
    for (int g = 0; g < RG; g++) idxr[g] = s_idx[g];
#pragma unroll
    for (int g = 0; g < RG; g++) {
        int r = base + g;
        float x = 0.f, nr = 0.f, dg = 1.f;
        if (r < totalRows) {
            x  = v2e[(size_t)idxr[g] * DD + j];
            nr = g_agg[(size_t)idxr[g] * DD + j];
            dg = g_deg[idxr[g]];
        }
        sx[g][j] = x;
        sn[g][j] = nr / fmaxf(dg, 1.0f);
    }
    __syncthreads();

    float bj = b_sage[j];
    float acc[RG];
#pragma unroll
    for (int g = 0; g < RG; g++) acc[g] = bj;
#pragma unroll 8
    for (int k = 0; k < DD; k++) {
        float ws = W_self[k * DD + j];
        float wn = W_neigh[k * DD + j];
#pragma unroll
        for (int g = 0; g < RG; g++)
            acc[g] = fmaf(sx[g][k], ws, fmaf(sn[g][k], wn, acc[g]));
    }
#pragma unroll 1
    for (int g = 0; g < RG; g++) {
        int r = base + g;
        if (r >= totalRows) continue;
        int b = r / (L + 1), s = r - b * (L + 1);
        float* outp = (s < L) ? (g_item_e + ((size_t)(b * L + s)) * DD)
                              : (g_user_e + (size_t)b * DD);
        float h1 = fmaxf(acc[g], 0.f);
        outp[j] = (h1 + sx[g][j]) * 0.5f;
    }
}

// ---------------- K5: fused session attention (R8 form, untouched) --------
__global__ void k_attn(const float* __restrict__ pos_w, const float* __restrict__ w1,
                       const float* __restrict__ w2, const float* __restrict__ glu1_w,
                       const float* __restrict__ glu1_b, const float* __restrict__ glu2_w,
                       const float* __restrict__ w3, const float* __restrict__ w4,
                       const float* __restrict__ glu3_w, const float* __restrict__ glu3_b,
                       const float* __restrict__ glu4_w, const float* __restrict__ wc_w,
                       const float* __restrict__ wc_b, const int* __restrict__ mask,
                       const int* __restrict__ pos_idx, int L) {
    int b = blockIdx.x, j = threadIdx.x;
    __shared__ float s_item[MAXL * DD], s_aux[MAXL * DD];
    __shared__ float s_user[DD], s_hs[DD];
    __shared__ float s_m[MAXL], s_beta[MAXL], s_rbuf[4], s_alpha;

    for (int l = 0; l < L; l++)
        s_item[l * DD + j] = g_item_e[((size_t)(b * L + l)) * DD + j];
    for (int l = L; l < MAXL; l++) s_item[l * DD + j] = 0.f;
    s_user[j] = g_user_e[(size_t)b * DD + j];
    if (j < MAXL) s_m[j] = (j < L) ? (float)mask[b * L + j] : 0.f;
    for (int l = 0; l < L; l++)
        s_aux[l * DD + j] = pos_w[(size_t)pos_idx[b * L + l] * DD + j];
    for (int l = L; l < MAXL; l++) s_aux[l * DD + j] = 0.f;
    __syncthreads();

    float msum = 0.f;
    for (int l = 0; l < MAXL; l++) msum += s_m[l];
    float hsv = 0.f;
    for (int l = 0; l < MAXL; l++) hsv += s_item[l * DD + j] * s_m[l];
    hsv /= msum;
    s_hs[j] = hsv;
    __syncthreads();

    float acc[MAXL];
#pragma unroll
    for (int l = 0; l < MAXL; l++) acc[l] = 0.f;
#pragma unroll 8
    for (int k = 0; k < DD; k++) {
        float w = w1[k * DD + j];
#pragma unroll
        for (int l = 0; l < MAXL; l++) acc[l] = fmaf(s_aux[l * DD + k], w, acc[l]);
    }
#pragma unroll 8
    for (int k = 0; k < DD; k++) {
        float w = w1[(DD + k) * DD + j];
#pragma unroll
        for (int l = 0; l < MAXL; l++) acc[l] = fmaf(s_item[l * DD + k], w, acc[l]);
    }
    __syncthreads();
#pragma unroll
    for (int l = 0; l < MAXL; l++) s_aux[l * DD + j] = tanhf(acc[l]);
    __syncthreads();

    float hsg = 0.f;
#pragma unroll 8
    for (int k = 0; k < DD; k++) hsg = fmaf(s_hs[k], glu2_w[k * DD + j], hsg);
#pragma unroll
    for (int l = 0; l < MAXL; l++) acc[l] = 0.f;
#pragma unroll 8
    for (int k = 0; k < DD; k++) {
        float g = glu1_w[k * DD + j];
#pragma unroll
        for (int l = 0; l < MAXL; l++) acc[l] = fmaf(s_aux[l * DD + k], g, acc[l]);
    }
    float w2j = w2[j], g1b = glu1_b[j];
    for (int l = 0; l < MAXL; l++) {
        float g1 = sigmoidf_(acc[l] + g1b + hsg);
        float tot = blockReduce128(g1 * w2j, s_rbuf);
        if (j == 0) s_beta[l] = tot * s_m[l];
    }
    __syncthreads();
    float sv = 0.f;
    for (int l = 0; l < MAXL; l++) sv = fmaf(s_beta[l], s_item[l * DD + j], sv);

#pragma unroll
    for (int l = 0; l < MAXL; l++) acc[l] = 0.f;
#pragma unroll 8
    for (int k = 0; k < DD; k++) {
        float w = w3[k * DD + j];
#pragma unroll
        for (int l = 0; l < MAXL; l++) acc[l] = fmaf(s_item[l * DD + k], w, acc[l]);
    }
    __syncthreads();
#pragma unroll
    for (int l = 0; l < MAXL; l++) s_aux[l * DD + j] = tanhf(acc[l]);
    __syncthreads();

    float ueg = 0.f;
#pragma unroll 8
    for (int k = 0; k < DD; k++) ueg = fmaf(s_user[k], glu4_w[k * DD + j], ueg);
#pragma unroll
    for (int l = 0; l < MAXL; l++) acc[l] = 0.f;
#pragma unroll 8
    for (int k = 0; k < DD; k++) {
        float g = glu3_w[k * DD + j];
#pragma unroll
        for (int l = 0; l < MAXL; l++) acc[l] = fmaf(s_aux[l * DD + k], g, acc[l]);
    }
    float w4j = w4[j], g3b = glu3_b[j];
    for (int l = 0; l < MAXL; l++) {
        float g3 = sigmoidf_(acc[l] + g3b + ueg);
        float tot = blockReduce128(g3 * w4j, s_rbuf);
        if (j == 0) s_beta[l] = tot * s_m[l];
    }
    __syncthreads();
    float su = 0.f;
    for (int l = 0; l < MAXL; l++) su = fmaf(s_beta[l], s_item[l * DD + j], su);

    float pa = sv * wc_w[j] + su * wc_w[DD + j];
    float asum = blockReduce128(pa, s_rbuf);
    if (j == 0) s_alpha = sigmoidf_(asum + wc_b[0]);
    __syncthreads();
    float alpha = s_alpha;
    g_seq_emb[(size_t)b * DD + j] = s_user[j] + alpha * sv + (1.0f - alpha) * su;
}

// ---------------- K5b: fp16 conversions ----------------
__global__ void k_split_v2e(const float* __restrict__ src, int n4) {
    int i = blockIdx.x * blockDim.x + threadIdx.x;
    if (i >= n4) return;
    float4 v = ((const float4*)src)[i];
    __half2* H = (__half2*)g_v2e_h;
    H[i * 2]     = __floats2half2_rn(v.x, v.y);
    H[i * 2 + 1] = __floats2half2_rn(v.z, v.w);
}
__global__ void k_split_seq(int n4) {
    int i = blockIdx.x * blockDim.x + threadIdx.x;
    if (i >= n4) return;
    float4 v = ((const float4*)g_seq_emb)[i];
    __half h0 = __float2half_rn(v.x), h1 = __float2half_rn(v.y);
    __half h2 = __float2half_rn(v.z), h3 = __float2half_rn(v.w);
    __half l0 = __float2half_rn(v.x - __half2float(h0));
    __half l1 = __float2half_rn(v.y - __half2float(h1));
    __half l2 = __float2half_rn(v.z - __half2float(h2));
    __half l3 = __float2half_rn(v.w - __half2float(h3));
    __half2* H = (__half2*)g_seq_hi;
    __half2* Lp = (__half2*)g_seq_lo;
    __half2 a; a.x = h0; a.y = h1; H[i * 2] = a;
    a.x = h2; a.y = h3; H[i * 2 + 1] = a;
    a.x = l0; a.y = l1; Lp[i * 2] = a;
    a.x = l2; a.y = l3; Lp[i * 2 + 1] = a;
}

// ---------------- K6: HMMA fp16x2-split GEMM: out = seq_emb @ v2e[1:]^T ----
#define TM 128
#define TN 64
#define ASTR 136
#define ROWB (ASTR * 2)            // 272 bytes
#define ATILEB (128 * ROWB)        // 34816
#define BTILEB (64 * ROWB)         // 17408
#define SA_HI 0
#define SA_LO ATILEB
#define SB    (2 * ATILEB)
#define SM_TOT (2 * ATILEB + BTILEB)   // 87040

__global__ void __launch_bounds__(256, 2)
k_gemm_mma(float* __restrict__ out, int N, int Nout, int BS) {
    extern __shared__ char smem[];
    uint32_t sb = smem_u32(smem);
    int tid = threadIdx.x;
    int wid = tid >> 5, lane = tid & 31;
    int bn = blockIdx.x, bm = blockIdx.y;
    int rowBase = bm * TM;
    int colBase = bn * TN;

    {
        const uint4* aH = (const uint4*)g_seq_hi;
        const uint4* aL = (const uint4*)g_seq_lo;
        uint4 z = make_uint4(0, 0, 0, 0);
        for (int i = tid; i < 128 * 16; i += 256) {
            int r = i >> 4, c = i & 15;
            uint32_t dst = (uint32_t)(r * ROWB + c * 16);
            int ga = rowBase + r;
            uint4 vh = z, vl = z;
            if (ga < BS) { vh = aH[ga * 16 + c]; vl = aL[ga * 16 + c]; }
            *(uint4*)(smem + SA_HI + dst) = vh;
            *(uint4*)(smem + SA_LO + dst) = vl;
        }
        const uint4* bH = (const uint4*)g_v2e_h;
        for (int i = tid; i < 64 * 16; i += 256) {
            int r = i >> 4, c = i & 15;
            uint32_t dst = (uint32_t)(r * ROWB + c * 16);
            int gb = 1 + colBase + r;
            uint4 wh = z;
            if (gb < N) wh = bH[(size_t)gb * 16 + c];
            *(uint4*)(smem + SB + dst) = wh;
        }
    }
    __syncthreads();

    int warp_m = (wid >> 1) * 32;
    int warp_n = (wid & 1) * 32;

    int a_row = (lane & 7) + ((lane >> 3) & 1) * 8;
    int a_k8  = ((lane >> 4) & 1) * 8;
    int b_row = (lane & 7) + ((lane >> 4) & 1) * 8;
    int b_k8  = ((lane >> 3) & 1) * 8;

    float acc[2][4][4];
#pragma unroll
    for (int mi = 0; mi < 2; mi++)
#pragma unroll
        for (int nb = 0; nb < 4; nb++)
#pragma unroll
            for (int q = 0; q < 4; q++) acc[mi][nb][q] = 0.f;

#pragma unroll
    for (int ks = 0; ks < 8; ks++) {
        int kc = ks * 16;
        uint32_t bb[8];
        {
            uint32_t addr0 = sb + SB + (uint32_t)((warp_n + b_row) * ROWB +
                                                  (kc + b_k8) * 2);
            ldsm_x4(bb[0], bb[1], bb[2], bb[3], addr0);
            uint32_t addr1 = addr0 + 16 * ROWB;
            ldsm_x4(bb[4], bb[5], bb[6], bb[7], addr1);
        }
#pragma unroll
        for (int t = 0; t < 2; t++) {
            uint32_t aBase = sb + (t == 0 ? SA_HI : SA_LO);
#pragma unroll
            for (int mi = 0; mi < 2; mi++) {
                uint32_t a0, a1, a2, a3;
                uint32_t addr = aBase + (uint32_t)((warp_m + mi * 16 + a_row) * ROWB +
                                                   (kc + a_k8) * 2);
                ldsm_x4(a0, a1, a2, a3, addr);
                mma16816(acc[mi][0], a0, a1, a2, a3, bb[0], bb[1]);
                mma16816(acc[mi][1], a0, a1, a2, a3, bb[2], bb[3]);
                mma16816(acc[mi][2], a0, a1, a2, a3, bb[4], bb[5]);
                mma16816(acc[mi][3], a0, a1, a2, a3, bb[6], bb[7]);
            }
        }
    }

    int grp = lane >> 2;
    int lc2 = (lane & 3) * 2;
#pragma unroll
    for (int mi = 0; mi < 2; mi++) {
        int r0 = rowBase + warp_m + mi * 16 + grp;
        if (r0 >= BS) continue;
        size_t ro0 = (size_t)r0 * (size_t)Nout;
        size_t ro1 = (size_t)(r0 + 8) * (size_t)Nout;
#pragma unroll
        for (int nb = 0; nb < 4; nb++) {
            int col = colBase + warp_n + nb * 8 + lc2;
            if (col < Nout)     out[ro0 + col]     = acc[mi][nb][0];
            if (col + 1 < Nout) out[ro0 + col + 1] = acc[mi][nb][1];
            if (col < Nout)     out[ro1 + col]     = acc[mi][nb][2];
            if (col + 1 < Nout) out[ro1 + col + 1] = acc[mi][nb][3];
        }
    }
}

// ---------------- launch ----------------
extern "C" void kernel_launch(void* const* d_in, const int* in_sizes, int n_in,
                              void* d_out, int out_size) {
    const int* user     = (const int*)d_in[0];
    const int* seq      = (const int*)d_in[1];
    const int* mask     = (const int*)d_in[2];
    const int* pos_idx  = (const int*)d_in[4];
    const int* edge_src = (const int*)d_in[5];
    const int* edge_dst = (const int*)d_in[6];
    const int* item_num = (const int*)d_in[7];
    const float* v2e    = (const float*)d_in[8];
    const float* pos_w  = (const float*)d_in[9];
    const float* W_self = (const float*)d_in[10];
    const float* W_neigh= (const float*)d_in[11];
    const float* b_sage = (const float*)d_in[12];
    const float* w1     = (const float*)d_in[13];
    const float* w2     = (const float*)d_in[14];
    const float* glu1_w = (const float*)d_in[15];
    const float* glu1_b = (const float*)d_in[16];
    const float* glu2_w = (const float*)d_in[17];
    const float* w3     = (const float*)d_in[18];
    const float* w4     = (const float*)d_in[19];
    const float* glu3_w = (const float*)d_in[20];
    const float* glu3_b = (const float*)d_in[21];
    const float* glu4_w = (const float*)d_in[22];
    const float* wc_w   = (const float*)d_in[23];
    const float* wc_b   = (const float*)d_in[24];
    float* out = (float*)d_out;

    int BS = in_sizes[0];
    int L  = in_sizes[1] / BS;
    int E  = in_sizes[5];
    int N  = in_sizes[8] / DD;
    int Nout = N - 1;

    k_zero<<<256, 256>>>(N);                                          // idx 0
    int tot = BS * L + BS;
    k_flags<<<(tot + 255) / 256, 256>>>(seq, user, item_num, BS, L);  // idx 1
    k_zero_agg<<<(N * 32 + 255) / 256, 256>>>(N);                     // idx 2
    k_scatter_fused<<<(E + 255) / 256, 256>>>(edge_src, edge_dst, v2e, E); // idx 3 (profiled)
    k_split_v2e<<<(N * DD / 4 + 255) / 256, 256>>>(v2e, N * DD / 4);  // idx 4
    int totalRows = BS * (L + 1);
    k_rows<<<(totalRows + RG - 1) / RG, 128>>>(v2e, W_self, W_neigh, b_sage,
                                               seq, user, item_num, L, totalRows);
    k_attn<<<BS, 128>>>(pos_w, w1, w2, glu1_w, glu1_b, glu2_w, w3, w4,
                        glu3_w, glu3_b, glu4_w, wc_w, wc_b, mask, pos_idx, L);
    k_split_seq<<<(BS * DD / 4 + 255) / 256, 256>>>(BS * DD / 4);

    cudaFuncSetAttribute(k_gemm_mma, cudaFuncAttributeMaxDynamicSharedMemorySize, SM_TOT);
    dim3 grid((Nout + TN - 1) / TN, (BS + TM - 1) / TM);
    k_gemm_mma<<<grid, 256, SM_TOT>>>(out, N, Nout, BS);
}

// round 15
// speedup vs baseline: 1.3332x; 1.0261x over previous
#include <cuda_runtime.h>
#include <cuda_fp16.h>
#include <cstdint>

#define DD 128
#define MAXN 50048
#define MAXB 512
#define MAXL 10

// ---------------- scratch (device globals; no allocation) ----------------
__device__ __align__(16) float g_agg[(size_t)MAXN * DD];
__device__ float g_deg[MAXN];
__device__ unsigned char g_flag[MAXN];
__device__ __align__(16) float g_item_e[(size_t)MAXB * MAXL * DD];
__device__ __align__(16) float g_user_e[(size_t)MAXB * DD];
__device__ __align__(16) float g_seq_emb[(size_t)MAXB * DD];
__device__ __align__(16) __half g_v2e_h[(size_t)MAXN * DD];
__device__ __align__(16) __half g_seq_hi[(size_t)MAXB * DD];
__device__ __align__(16) __half g_seq_lo[(size_t)MAXB * DD];

// ---------------- helpers ----------------
__device__ __forceinline__ float warpReduce(float v) {
    v += __shfl_down_sync(0xffffffffu, v, 16);
    v += __shfl_down_sync(0xffffffffu, v, 8);
    v += __shfl_down_sync(0xffffffffu, v, 4);
    v += __shfl_down_sync(0xffffffffu, v, 2);
    v += __shfl_down_sync(0xffffffffu, v, 1);
    return v;
}
__device__ __forceinline__ float blockReduce128(float v, float* buf) {
    int tid = threadIdx.x;
    __syncthreads();
    float w = warpReduce(v);
    if ((tid & 31) == 0) buf[tid >> 5] = w;
    __syncthreads();
    return buf[0] + buf[1] + buf[2] + buf[3];
}
__device__ __forceinline__ float sigmoidf_(float x) {
    return 1.0f / (1.0f + expf(-x));
}
__device__ __forceinline__ uint32_t smem_u32(const void* p) {
    uint32_t a;
    asm("{ .reg .u64 t; cvta.to.shared.u64 t, %1; cvt.u32.u64 %0, t; }" : "=r"(a) : "l"(p));
    return a;
}

// ---------------- mma.sync / ldmatrix (baseline PTX, sm_80+) ----------------
__device__ __forceinline__ void ldsm_x4(uint32_t& r0, uint32_t& r1, uint32_t& r2,
                                        uint32_t& r3, uint32_t addr) {
    asm volatile("ldmatrix.sync.aligned.m8n8.x4.shared.b16 {%0,%1,%2,%3}, [%4];"
                 : "=r"(r0), "=r"(r1), "=r"(r2), "=r"(r3) : "r"(addr));
}
__device__ __forceinline__ void mma16816(float* c, uint32_t a0, uint32_t a1,
                                         uint32_t a2, uint32_t a3,
                                         uint32_t b0, uint32_t b1) {
    asm volatile(
        "mma.sync.aligned.m16n8k16.row.col.f32.f16.f16.f32 "
        "{%0,%1,%2,%3}, {%4,%5,%6,%7}, {%8,%9}, {%0,%1,%2,%3};"
        : "+f"(c[0]), "+f"(c[1]), "+f"(c[2]), "+f"(c[3])
        : "r"(a0), "r"(a1), "r"(a2), "r"(a3), "r"(b0), "r"(b1));
}

// ---------------- K0: zero deg/flag ----------------
__global__ void k_zero(int N) {
    int gid = blockIdx.x * blockDim.x + threadIdx.x;
    int stride = gridDim.x * blockDim.x;
    for (int i = gid; i < N; i += stride) { g_deg[i] = 0.f; g_flag[i] = 0; }
}

// ---------------- K1: flag needed nodes ----------------
__global__ void k_flags(const int* __restrict__ seq, const int* __restrict__ user,
                        const int* __restrict__ item_num, int BS, int L) {
    int t = blockIdx.x * blockDim.x + threadIdx.x;
    int total = BS * L + BS;
    if (t >= total) return;
    if (t < BS * L) g_flag[seq[t]] = 1;
    else            g_flag[user[t - BS * L] + item_num[0]] = 1;
}

// ---------------- K1b: zero agg rows only where flagged ----------------
__global__ void k_zero_agg(int N) {
    int gw = (blockIdx.x * blockDim.x + threadIdx.x) >> 5;
    int lane = threadIdx.x & 31;
    if (gw >= N) return;
    if (g_flag[gw]) {
        float4 z = make_float4(0.f, 0.f, 0.f, 0.f);
        ((float4*)(g_agg + (size_t)gw * DD))[lane] = z;
    }
}

// ---------------- K2: fused flag-check + scatter (ballot, scalar atomics) --
__global__ void k_scatter_fused(const int* __restrict__ edge_src,
                                const int* __restrict__ edge_dst,
                                const float* __restrict__ v2e, int E) {
    int lane = threadIdx.x & 31;
    int e = blockIdx.x * blockDim.x + threadIdx.x;
    bool p = false;
    int dst = 0;
    if (e < E) { dst = edge_dst[e]; p = (g_flag[dst] != 0); }
    unsigned m = __ballot_sync(0xffffffffu, p);
    while (m) {
        int src_lane = __ffs(m) - 1;
        m &= m - 1;
        int dd = __shfl_sync(0xffffffffu, dst, src_lane);
        int ee = __shfl_sync(0xffffffffu, e, src_lane);
        int src = edge_src[ee];
        float4 v = ((const float4*)(v2e + (size_t)src * DD))[lane];
        float* a = g_agg + (size_t)dd * DD + lane * 4;
        atomicAdd(a + 0, v.x);
        atomicAdd(a + 1, v.y);
        atomicAdd(a + 2, v.z);
        atomicAdd(a + 3, v.w);
        if (lane == src_lane) atomicAdd(&g_deg[dd], 1.0f);
    }
}

// ---------------- K4: SAGE rows, 16 rows/block ----------------------------
#define RG 16
__global__ void k_rows(const float* __restrict__ v2e, const float* __restrict__ W_self,
                       const float* __restrict__ W_neigh, const float* __restrict__ b_sage,
                       const int* __restrict__ seq, const int* __restrict__ user,
                       const int* __restrict__ item_num, int L, int totalRows) {
    __shared__ float sx[RG][DD], sn[RG][DD];
    __shared__ int s_idx[RG];
    int j = threadIdx.x;
    int base = blockIdx.x * RG;

    if (j < RG) {
        int r = base + j;
        int idx = 0;
        if (r < totalRows) {
            int b = r / (L + 1), s = r - b * (L + 1);
            idx = (s < L) ? seq[b * L + s] : (user[b] + item_num[0]);
        }
        s_idx[j] = idx;
    }
    __syncthreads();

    int idxr[RG];
#pragma unroll
    for (int g = 0; g < RG; g++) idxr[g] = s_idx[g];
#pragma unroll
    for (int g = 0; g < RG; g++) {
        int r = base + g;
        float x = 0.f, nr = 0.f, dg = 1.f;
        if (r < totalRows) {
            x  = v2e[(size_t)idxr[g] * DD + j];
            nr = g_agg[(size_t)idxr[g] * DD + j];
            dg = g_deg[idxr[g]];
        }
        sx[g][j] = x;
        sn[g][j] = nr / fmaxf(dg, 1.0f);
    }
    __syncthreads();

    float bj = b_sage[j];
    float acc[RG];
#pragma unroll
    for (int g = 0; g < RG; g++) acc[g] = bj;
#pragma unroll 8
    for (int k = 0; k < DD; k++) {
        float ws = W_self[k * DD + j];
        float wn = W_neigh[k * DD + j];
#pragma unroll
        for (int g = 0; g < RG; g++)
            acc[g] = fmaf(sx[g][k], ws, fmaf(sn[g][k], wn, acc[g]));
    }
#pragma unroll 1
    for (int g = 0; g < RG; g++) {
        int r = base + g;
        if (r >= totalRows) continue;
        int b = r / (L + 1), s = r - b * (L + 1);
        float* outp = (s < L) ? (g_item_e + ((size_t)(b * L + s)) * DD)
                              : (g_user_e + (size_t)b * DD);
        float h1 = fmaxf(acc[g], 0.f);
        outp[j] = (h1 + sx[g][j]) * 0.5f;
    }
}

// ---------------- K5: fused session attention (R8 form, untouched) --------
__global__ void k_attn(const float* __restrict__ pos_w, const float* __restrict__ w1,
                       const float* __restrict__ w2, const float* __restrict__ glu1_w,
                       const float* __restrict__ glu1_b, const float* __restrict__ glu2_w,
                       const float* __restrict__ w3, const float* __restrict__ w4,
                       const float* __restrict__ glu3_w, const float* __restrict__ glu3_b,
                       const float* __restrict__ glu4_w, const float* __restrict__ wc_w,
                       const float* __restrict__ wc_b, const int* __restrict__ mask,
                       const int* __restrict__ pos_idx, int L) {
    int b = blockIdx.x, j = threadIdx.x;
    __shared__ float s_item[MAXL * DD], s_aux[MAXL * DD];
    __shared__ float s_user[DD], s_hs[DD];
    __shared__ float s_m[MAXL], s_beta[MAXL], s_rbuf[4], s_alpha;

    for (int l = 0; l < L; l++)
        s_item[l * DD + j] = g_item_e[((size_t)(b * L + l)) * DD + j];
    for (int l = L; l < MAXL; l++) s_item[l * DD + j] = 0.f;
    s_user[j] = g_user_e[(size_t)b * DD + j];
    if (j < MAXL) s_m[j] = (j < L) ? (float)mask[b * L + j] : 0.f;
    for (int l = 0; l < L; l++)
        s_aux[l * DD + j] = pos_w[(size_t)pos_idx[b * L + l] * DD + j];
    for (int l = L; l < MAXL; l++) s_aux[l * DD + j] = 0.f;
    __syncthreads();

    float msum = 0.f;
    for (int l = 0; l < MAXL; l++) msum += s_m[l];
    float hsv = 0.f;
    for (int l = 0; l < MAXL; l++) hsv += s_item[l * DD + j] * s_m[l];
    hsv /= msum;
    s_hs[j] = hsv;
    __syncthreads();

    float acc[MAXL];
#pragma unroll
    for (int l = 0; l < MAXL; l++) acc[l] = 0.f;
#pragma unroll 8
    for (int k = 0; k < DD; k++) {
        float w = w1[k * DD + j];
#pragma unroll
        for (int l = 0; l < MAXL; l++) acc[l] = fmaf(s_aux[l * DD + k], w, acc[l]);
    }
#pragma unroll 8
    for (int k = 0; k < DD; k++) {
        float w = w1[(DD + k) * DD + j];
#pragma unroll
        for (int l = 0; l < MAXL; l++) acc[l] = fmaf(s_item[l * DD + k], w, acc[l]);
    }
    __syncthreads();
#pragma unroll
    for (int l = 0; l < MAXL; l++) s_aux[l * DD + j] = tanhf(acc[l]);
    __syncthreads();

    float hsg = 0.f;
#pragma unroll 8
    for (int k = 0; k < DD; k++) hsg = fmaf(s_hs[k], glu2_w[k * DD + j], hsg);
#pragma unroll
    for (int l = 0; l < MAXL; l++) acc[l] = 0.f;
#pragma unroll 8
    for (int k = 0; k < DD; k++) {
        float g = glu1_w[k * DD + j];
#pragma unroll
        for (int l = 0; l < MAXL; l++) acc[l] = fmaf(s_aux[l * DD + k], g, acc[l]);
    }
    float w2j = w2[j], g1b = glu1_b[j];
    for (int l = 0; l < MAXL; l++) {
        float g1 = sigmoidf_(acc[l] + g1b + hsg);
        float tot = blockReduce128(g1 * w2j, s_rbuf);
        if (j == 0) s_beta[l] = tot * s_m[l];
    }
    __syncthreads();
    float sv = 0.f;
    for (int l = 0; l < MAXL; l++) sv = fmaf(s_beta[l], s_item[l * DD + j], sv);

#pragma unroll
    for (int l = 0; l < MAXL; l++) acc[l] = 0.f;
#pragma unroll 8
    for (int k = 0; k < DD; k++) {
        float w = w3[k * DD + j];
#pragma unroll
        for (int l = 0; l < MAXL; l++) acc[l] = fmaf(s_item[l * DD + k], w, acc[l]);
    }
    __syncthreads();
#pragma unroll
    for (int l = 0; l < MAXL; l++) s_aux[l * DD + j] = tanhf(acc[l]);
    __syncthreads();

    float ueg = 0.f;
#pragma unroll 8
    for (int k = 0; k < DD; k++) ueg = fmaf(s_user[k], glu4_w[k * DD + j], ueg);
#pragma unroll
    for (int l = 0; l < MAXL; l++) acc[l] = 0.f;
#pragma unroll 8
    for (int k = 0; k < DD; k++) {
        float g = glu3_w[k * DD + j];
#pragma unroll
        for (int l = 0; l < MAXL; l++) acc[l] = fmaf(s_aux[l * DD + k], g, acc[l]);
    }
    float w4j = w4[j], g3b = glu3_b[j];
    for (int l = 0; l < MAXL; l++) {
        float g3 = sigmoidf_(acc[l] + g3b + ueg);
        float tot = blockReduce128(g3 * w4j, s_rbuf);
        if (j == 0) s_beta[l] = tot * s_m[l];
    }
    __syncthreads();
    float su = 0.f;
    for (int l = 0; l < MAXL; l++) su = fmaf(s_beta[l], s_item[l * DD + j], su);

    float pa = sv * wc_w[j] + su * wc_w[DD + j];
    float asum = blockReduce128(pa, s_rbuf);
    if (j == 0) s_alpha = sigmoidf_(asum + wc_b[0]);
    __syncthreads();
    float alpha = s_alpha;
    g_seq_emb[(size_t)b * DD + j] = s_user[j] + alpha * sv + (1.0f - alpha) * su;
}

// ---------------- K5b: fp16 conversions ----------------
__global__ void k_split_v2e(const float* __restrict__ src, int n4) {
    int i = blockIdx.x * blockDim.x + threadIdx.x;
    if (i >= n4) return;
    float4 v = ((const float4*)src)[i];
    __half2* H = (__half2*)g_v2e_h;
    H[i * 2]     = __floats2half2_rn(v.x, v.y);
    H[i * 2 + 1] = __floats2half2_rn(v.z, v.w);
}
__global__ void k_split_seq(int n4) {
    int i = blockIdx.x * blockDim.x + threadIdx.x;
    if (i >= n4) return;
    float4 v = ((const float4*)g_seq_emb)[i];
    __half h0 = __float2half_rn(v.x), h1 = __float2half_rn(v.y);
    __half h2 = __float2half_rn(v.z), h3 = __float2half_rn(v.w);
    __half l0 = __float2half_rn(v.x - __half2float(h0));
    __half l1 = __float2half_rn(v.y - __half2float(h1));
    __half l2 = __float2half_rn(v.z - __half2float(h2));
    __half l3 = __float2half_rn(v.w - __half2float(h3));
    __half2* H = (__half2*)g_seq_hi;
    __half2* Lp = (__half2*)g_seq_lo;
    __half2 a; a.x = h0; a.y = h1; H[i * 2] = a;
    a.x = h2; a.y = h3; H[i * 2 + 1] = a;
    a.x = l0; a.y = l1; Lp[i * 2] = a;
    a.x = l2; a.y = l3; Lp[i * 2 + 1] = a;
}

// ---------------- K6: HMMA fp16x2-split GEMM, 128x128 tile, 2 CTAs/SM -----
#define TM 128
#define TN 128
#define ASTR 136
#define ROWB (ASTR * 2)            // 272 bytes
#define TILEB (128 * ROWB)         // 34816
#define SA_HI 0
#define SA_LO TILEB
#define SB    (2 * TILEB)
#define SM_TOT (3 * TILEB)         // 104448

__global__ void __launch_bounds__(256, 2)
k_gemm_mma(float* __restrict__ out, int N, int Nout, int BS) {
    extern __shared__ char smem[];
    uint32_t sb = smem_u32(smem);
    int tid = threadIdx.x;
    int wid = tid >> 5, lane = tid & 31;
    int bn = blockIdx.x, bm = blockIdx.y;
    int rowBase = bm * TM;
    int colBase = bn * TN;

    // ---- global -> smem: A hi/lo (128 rows), B (128 rows) ----
    {
        const uint4* aH = (const uint4*)g_seq_hi;
        const uint4* aL = (const uint4*)g_seq_lo;
        const uint4* bH = (const uint4*)g_v2e_h;
        uint4 z = make_uint4(0, 0, 0, 0);
        for (int i = tid; i < 128 * 16; i += 256) {
            int r = i >> 4, c = i & 15;
            uint32_t dst = (uint32_t)(r * ROWB + c * 16);
            int ga = rowBase + r;
            uint4 vh = z, vl = z;
            if (ga < BS) { vh = aH[ga * 16 + c]; vl = aL[ga * 16 + c]; }
            *(uint4*)(smem + SA_HI + dst) = vh;
            *(uint4*)(smem + SA_LO + dst) = vl;
            int gb = 1 + colBase + r;
            uint4 wh = z;
            if (gb < N) wh = bH[(size_t)gb * 16 + c];
            *(uint4*)(smem + SB + dst) = wh;
        }
    }
    __syncthreads();

    // warp layout: 2 (m) x 4 (n); warp tile 64 x 32
    int warp_m = (wid >> 2) * 64;
    int warp_n = (wid & 3) * 32;

    int a_row = (lane & 7) + ((lane >> 3) & 1) * 8;
    int a_k8  = ((lane >> 4) & 1) * 8;
    int b_row = (lane & 7) + ((lane >> 4) & 1) * 8;
    int b_k8  = ((lane >> 3) & 1) * 8;

    float acc[2][4][4][4];   // [t? no: mi over 4][...] -> [hi/lo folded]: mi(4) x nb(4) x 4
    // NOTE: we fold hi/lo into the same accumulators (sum of terms), so acc[4][4][4].
    float accm[4][4][4];
#pragma unroll
    for (int mi = 0; mi < 4; mi++)
#pragma unroll
        for (int nb = 0; nb < 4; nb++)
#pragma unroll
            for (int q = 0; q < 4; q++) accm[mi][nb][q] = 0.f;
    (void)acc;

#pragma unroll
    for (int ks = 0; ks < 8; ks++) {
        int kc = ks * 16;
        // B frags loaded ONCE per k-step, shared by both A terms
        uint32_t bb[8];
        {
            uint32_t addr0 = sb + SB + (uint32_t)((warp_n + b_row) * ROWB +
                                                  (kc + b_k8) * 2);
            ldsm_x4(bb[0], bb[1], bb[2], bb[3], addr0);
            uint32_t addr1 = addr0 + 16 * ROWB;
            ldsm_x4(bb[4], bb[5], bb[6], bb[7], addr1);
        }
#pragma unroll
        for (int t = 0; t < 2; t++) {
            uint32_t aBase = sb + (t == 0 ? SA_HI : SA_LO);
#pragma unroll
            for (int mi = 0; mi < 4; mi++) {
                uint32_t a0, a1, a2, a3;
                uint32_t addr = aBase + (uint32_t)((warp_m + mi * 16 + a_row) * ROWB +
                                                   (kc + a_k8) * 2);
                ldsm_x4(a0, a1, a2, a3, addr);
                mma16816(accm[mi][0], a0, a1, a2, a3, bb[0], bb[1]);
                mma16816(accm[mi][1], a0, a1, a2, a3, bb[2], bb[3]);
                mma16816(accm[mi][2], a0, a1, a2, a3, bb[4], bb[5]);
                mma16816(accm[mi][3], a0, a1, a2, a3, bb[6], bb[7]);
            }
        }
    }

    // epilogue: scalar f32 stores (Nout odd => odd rows only 4B-aligned)
    int grp = lane >> 2;
    int lc2 = (lane & 3) * 2;
#pragma unroll
    for (int mi = 0; mi < 4; mi++) {
        int r0 = rowBase + warp_m + mi * 16 + grp;
        if (r0 >= BS) continue;
        size_t ro0 = (size_t)r0 * (size_t)Nout;
        size_t ro1 = (size_t)(r0 + 8) * (size_t)Nout;
#pragma unroll
        for (int nb = 0; nb < 4; nb++) {
            int col = colBase + warp_n + nb * 8 + lc2;
            if (col < Nout)     out[ro0 + col]     = accm[mi][nb][0];
            if (col + 1 < Nout) out[ro0 + col + 1] = accm[mi][nb][1];
            if (col < Nout)     out[ro1 + col]     = accm[mi][nb][2];
            if (col + 1 < Nout) out[ro1 + col + 1] = accm[mi][nb][3];
        }
    }
}

// ---------------- launch ----------------
extern "C" void kernel_launch(void* const* d_in, const int* in_sizes, int n_in,
                              void* d_out, int out_size) {
    const int* user     = (const int*)d_in[0];
    const int* seq      = (const int*)d_in[1];
    const int* mask     = (const int*)d_in[2];
    const int* pos_idx  = (const int*)d_in[4];
    const int* edge_src = (const int*)d_in[5];
    const int* edge_dst = (const int*)d_in[6];
    const int* item_num = (const int*)d_in[7];
    const float* v2e    = (const float*)d_in[8];
    const float* pos_w  = (const float*)d_in[9];
    const float* W_self = (const float*)d_in[10];
    const float* W_neigh= (const float*)d_in[11];
    const float* b_sage = (const float*)d_in[12];
    const float* w1     = (const float*)d_in[13];
    const float* w2     = (const float*)d_in[14];
    const float* glu1_w = (const float*)d_in[15];
    const float* glu1_b = (const float*)d_in[16];
    const float* glu2_w = (const float*)d_in[17];
    const float* w3     = (const float*)d_in[18];
    const float* w4     = (const float*)d_in[19];
    const float* glu3_w = (const float*)d_in[20];
    const float* glu3_b = (const float*)d_in[21];
    const float* glu4_w = (const float*)d_in[22];
    const float* wc_w   = (const float*)d_in[23];
    const float* wc_b   = (const float*)d_in[24];
    float* out = (float*)d_out;

    int BS = in_sizes[0];
    int L  = in_sizes[1] / BS;
    int E  = in_sizes[5];
    int N  = in_sizes[8] / DD;
    int Nout = N - 1;

    k_zero<<<256, 256>>>(N);                                          // idx 0
    int tot = BS * L + BS;
    k_flags<<<(tot + 255) / 256, 256>>>(seq, user, item_num, BS, L);  // idx 1
    k_zero_agg<<<(N * 32 + 255) / 256, 256>>>(N);                     // idx 2
    k_scatter_fused<<<(E + 255) / 256, 256>>>(edge_src, edge_dst, v2e, E); // idx 3
    k_split_v2e<<<(N * DD / 4 + 255) / 256, 256>>>(v2e, N * DD / 4);  // idx 4
    int totalRows = BS * (L + 1);
    k_rows<<<(totalRows + RG - 1) / RG, 128>>>(v2e, W_self, W_neigh, b_sage,
                                               seq, user, item_num, L, totalRows);
    k_attn<<<BS, 128>>>(pos_w, w1, w2, glu1_w, glu1_b, glu2_w, w3, w4,
                        glu3_w, glu3_b, glu4_w, wc_w, wc_b, mask, pos_idx, L);
    k_split_seq<<<(BS * DD / 4 + 255) / 256, 256>>>(BS * DD / 4);

    cudaFuncSetAttribute(k_gemm_mma, cudaFuncAttributeMaxDynamicSharedMemorySize, SM_TOT);
    dim3 grid((Nout + TN - 1) / TN, (BS + TM - 1) / TM);
    k_gemm_mma<<<grid, 256, SM_TOT>>>(out, N, Nout, BS);
}

// round 16
// speedup vs baseline: 1.3800x; 1.0351x over previous
#include <cuda_runtime.h>
#include <cuda_fp16.h>
#include <cstdint>

#define DD 128
#define MAXN 50048
#define MAXB 512
#define MAXL 10

// ---------------- scratch (device globals; no allocation) ----------------
// NOTE: g_flag relies on zero-init at module load; k_rows clears the flags it
// used, restoring the all-zero invariant before every subsequent call/replay.
__device__ __align__(16) float g_agg[(size_t)MAXN * DD];
__device__ float g_deg[MAXN];
__device__ unsigned char g_flag[MAXN];
__device__ __align__(16) float g_item_e[(size_t)MAXB * MAXL * DD];
__device__ __align__(16) float g_user_e[(size_t)MAXB * DD];
__device__ __align__(16) __half g_v2e_h[(size_t)MAXN * DD];
__device__ __align__(16) __half g_seq_hi[(size_t)MAXB * DD];
__device__ __align__(16) __half g_seq_lo[(size_t)MAXB * DD];

// ---------------- helpers ----------------
__device__ __forceinline__ float warpReduce(float v) {
    v += __shfl_down_sync(0xffffffffu, v, 16);
    v += __shfl_down_sync(0xffffffffu, v, 8);
    v += __shfl_down_sync(0xffffffffu, v, 4);
    v += __shfl_down_sync(0xffffffffu, v, 2);
    v += __shfl_down_sync(0xffffffffu, v, 1);
    return v;
}
__device__ __forceinline__ float blockReduce128(float v, float* buf) {
    int tid = threadIdx.x;
    __syncthreads();
    float w = warpReduce(v);
    if ((tid & 31) == 0) buf[tid >> 5] = w;
    __syncthreads();
    return buf[0] + buf[1] + buf[2] + buf[3];
}
__device__ __forceinline__ float sigmoidf_(float x) {
    return 1.0f / (1.0f + expf(-x));
}
__device__ __forceinline__ uint32_t smem_u32(const void* p) {
    uint32_t a;
    asm("{ .reg .u64 t; cvta.to.shared.u64 t, %1; cvt.u32.u64 %0, t; }" : "=r"(a) : "l"(p));
    return a;
}

// ---------------- mma.sync / ldmatrix (baseline PTX, sm_80+) ----------------
__device__ __forceinline__ void ldsm_x4(uint32_t& r0, uint32_t& r1, uint32_t& r2,
                                        uint32_t& r3, uint32_t addr) {
    asm volatile("ldmatrix.sync.aligned.m8n8.x4.shared.b16 {%0,%1,%2,%3}, [%4];"
                 : "=r"(r0), "=r"(r1), "=r"(r2), "=r"(r3) : "r"(addr));
}
__device__ __forceinline__ void mma16816(float* c, uint32_t a0, uint32_t a1,
                                         uint32_t a2, uint32_t a3,
                                         uint32_t b0, uint32_t b1) {
    asm volatile(
        "mma.sync.aligned.m16n8k16.row.col.f32.f16.f16.f32 "
        "{%0,%1,%2,%3}, {%4,%5,%6,%7}, {%8,%9}, {%0,%1,%2,%3};"
        : "+f"(c[0]), "+f"(c[1]), "+f"(c[2]), "+f"(c[3])
        : "r"(a0), "r"(a1), "r"(a2), "r"(a3), "r"(b0), "r"(b1));
}

// ---------------- K1: flag needed nodes + zero their agg/deg (idempotent) --
__global__ void k_flags_zero(const int* __restrict__ seq, const int* __restrict__ user,
                             const int* __restrict__ item_num, int BS, int L) {
    int w = (blockIdx.x * blockDim.x + threadIdx.x) >> 5;
    int lane = threadIdx.x & 31;
    int total = BS * L + BS;
    if (w >= total) return;
    int idx = (w < BS * L) ? seq[w] : (user[w - BS * L] + item_num[0]);
    if (lane == 0) { g_flag[idx] = 1; g_deg[idx] = 0.f; }
    float4 z = make_float4(0.f, 0.f, 0.f, 0.f);
    ((float4*)(g_agg + (size_t)idx * DD))[lane] = z;  // dup zero-writes benign
}

// ---------------- K2: fused flag-check + scatter (ballot, scalar atomics) --
__global__ void k_scatter_fused(const int* __restrict__ edge_src,
                                const int* __restrict__ edge_dst,
                                const float* __restrict__ v2e, int E) {
    int lane = threadIdx.x & 31;
    int e = blockIdx.x * blockDim.x + threadIdx.x;
    bool p = false;
    int dst = 0;
    if (e < E) { dst = edge_dst[e]; p = (g_flag[dst] != 0); }
    unsigned m = __ballot_sync(0xffffffffu, p);
    while (m) {
        int src_lane = __ffs(m) - 1;
        m &= m - 1;
        int dd = __shfl_sync(0xffffffffu, dst, src_lane);
        int ee = __shfl_sync(0xffffffffu, e, src_lane);
        int src = edge_src[ee];
        float4 v = ((const float4*)(v2e + (size_t)src * DD))[lane];
        float* a = g_agg + (size_t)dd * DD + lane * 4;
        atomicAdd(a + 0, v.x);
        atomicAdd(a + 1, v.y);
        atomicAdd(a + 2, v.z);
        atomicAdd(a + 3, v.w);
        if (lane == src_lane) atomicAdd(&g_deg[dd], 1.0f);
    }
}

// ---------------- K4: SAGE rows, 16 rows/block; clears flags after use ----
#define RG 16
__global__ void k_rows(const float* __restrict__ v2e, const float* __restrict__ W_self,
                       const float* __restrict__ W_neigh, const float* __restrict__ b_sage,
                       const int* __restrict__ seq, const int* __restrict__ user,
                       const int* __restrict__ item_num, int L, int totalRows) {
    __shared__ float sx[RG][DD], sn[RG][DD];
    __shared__ int s_idx[RG];
    int j = threadIdx.x;
    int base = blockIdx.x * RG;

    if (j < RG) {
        int r = base + j;
        int idx = 0;
        if (r < totalRows) {
            int b = r / (L + 1), s = r - b * (L + 1);
            idx = (s < L) ? seq[b * L + s] : (user[b] + item_num[0]);
        }
        s_idx[j] = idx;
    }
    __syncthreads();

    int idxr[RG];
#pragma unroll
    for (int g = 0; g < RG; g++) idxr[g] = s_idx[g];
#pragma unroll
    for (int g = 0; g < RG; g++) {
        int r = base + g;
        float x = 0.f, nr = 0.f, dg = 1.f;
        if (r < totalRows) {
            x  = v2e[(size_t)idxr[g] * DD + j];
            nr = g_agg[(size_t)idxr[g] * DD + j];
            dg = g_deg[idxr[g]];
        }
        sx[g][j] = x;
        sn[g][j] = nr / fmaxf(dg, 1.0f);
    }
    __syncthreads();

    // restore g_flag == 0 invariant for next replay (dup clears benign)
    if (j < RG && base + j < totalRows) g_flag[s_idx[j]] = 0;

    float bj = b_sage[j];
    float acc[RG];
#pragma unroll
    for (int g = 0; g < RG; g++) acc[g] = bj;
#pragma unroll 8
    for (int k = 0; k < DD; k++) {
        float ws = W_self[k * DD + j];
        float wn = W_neigh[k * DD + j];
#pragma unroll
        for (int g = 0; g < RG; g++)
            acc[g] = fmaf(sx[g][k], ws, fmaf(sn[g][k], wn, acc[g]));
    }
#pragma unroll 1
    for (int g = 0; g < RG; g++) {
        int r = base + g;
        if (r >= totalRows) continue;
        int b = r / (L + 1), s = r - b * (L + 1);
        float* outp = (s < L) ? (g_item_e + ((size_t)(b * L + s)) * DD)
                              : (g_user_e + (size_t)b * DD);
        float h1 = fmaxf(acc[g], 0.f);
        outp[j] = (h1 + sx[g][j]) * 0.5f;
    }
}

// ---------------- K5: fused session attention + direct fp16 split out -----
__global__ void k_attn(const float* __restrict__ pos_w, const float* __restrict__ w1,
                       const float* __restrict__ w2, const float* __restrict__ glu1_w,
                       const float* __restrict__ glu1_b, const float* __restrict__ glu2_w,
                       const float* __restrict__ w3, const float* __restrict__ w4,
                       const float* __restrict__ glu3_w, const float* __restrict__ glu3_b,
                       const float* __restrict__ glu4_w, const float* __restrict__ wc_w,
                       const float* __restrict__ wc_b, const int* __restrict__ mask,
                       const int* __restrict__ pos_idx, int L) {
    int b = blockIdx.x, j = threadIdx.x;
    __shared__ float s_item[MAXL * DD], s_aux[MAXL * DD];
    __shared__ float s_user[DD], s_hs[DD];
    __shared__ float s_m[MAXL], s_beta[MAXL], s_rbuf[4], s_alpha;

    for (int l = 0; l < L; l++)
        s_item[l * DD + j] = g_item_e[((size_t)(b * L + l)) * DD + j];
    for (int l = L; l < MAXL; l++) s_item[l * DD + j] = 0.f;
    s_user[j] = g_user_e[(size_t)b * DD + j];
    if (j < MAXL) s_m[j] = (j < L) ? (float)mask[b * L + j] : 0.f;
    for (int l = 0; l < L; l++)
        s_aux[l * DD + j] = pos_w[(size_t)pos_idx[b * L + l] * DD + j];
    for (int l = L; l < MAXL; l++) s_aux[l * DD + j] = 0.f;
    __syncthreads();

    float msum = 0.f;
    for (int l = 0; l < MAXL; l++) msum += s_m[l];
    float hsv = 0.f;
    for (int l = 0; l < MAXL; l++) hsv += s_item[l * DD + j] * s_m[l];
    hsv /= msum;
    s_hs[j] = hsv;
    __syncthreads();

    float acc[MAXL];
#pragma unroll
    for (int l = 0; l < MAXL; l++) acc[l] = 0.f;
#pragma unroll 8
    for (int k = 0; k < DD; k++) {
        float w = w1[k * DD + j];
#pragma unroll
        for (int l = 0; l < MAXL; l++) acc[l] = fmaf(s_aux[l * DD + k], w, acc[l]);
    }
#pragma unroll 8
    for (int k = 0; k < DD; k++) {
        float w = w1[(DD + k) * DD + j];
#pragma unroll
        for (int l = 0; l < MAXL; l++) acc[l] = fmaf(s_item[l * DD + k], w, acc[l]);
    }
    __syncthreads();
#pragma unroll
    for (int l = 0; l < MAXL; l++) s_aux[l * DD + j] = tanhf(acc[l]);
    __syncthreads();

    float hsg = 0.f;
#pragma unroll 8
    for (int k = 0; k < DD; k++) hsg = fmaf(s_hs[k], glu2_w[k * DD + j], hsg);
#pragma unroll
    for (int l = 0; l < MAXL; l++) acc[l] = 0.f;
#pragma unroll 8
    for (int k = 0; k < DD; k++) {
        float g = glu1_w[k * DD + j];
#pragma unroll
        for (int l = 0; l < MAXL; l++) acc[l] = fmaf(s_aux[l * DD + k], g, acc[l]);
    }
    float w2j = w2[j], g1b = glu1_b[j];
    for (int l = 0; l < MAXL; l++) {
        float g1 = sigmoidf_(acc[l] + g1b + hsg);
        float tot = blockReduce128(g1 * w2j, s_rbuf);
        if (j == 0) s_beta[l] = tot * s_m[l];
    }
    __syncthreads();
    float sv = 0.f;
    for (int l = 0; l < MAXL; l++) sv = fmaf(s_beta[l], s_item[l * DD + j], sv);

#pragma unroll
    for (int l = 0; l < MAXL; l++) acc[l] = 0.f;
#pragma unroll 8
    for (int k = 0; k < DD; k++) {
        float w = w3[k * DD + j];
#pragma unroll
        for (int l = 0; l < MAXL; l++) acc[l] = fmaf(s_item[l * DD + k], w, acc[l]);
    }
    __syncthreads();
#pragma unroll
    for (int l = 0; l < MAXL; l++) s_aux[l * DD + j] = tanhf(acc[l]);
    __syncthreads();

    float ueg = 0.f;
#pragma unroll 8
    for (int k = 0; k < DD; k++) ueg = fmaf(s_user[k], glu4_w[k * DD + j], ueg);
#pragma unroll
    for (int l = 0; l < MAXL; l++) acc[l] = 0.f;
#pragma unroll 8
    for (int k = 0; k < DD; k++) {
        float g = glu3_w[k * DD + j];
#pragma unroll
        for (int l = 0; l < MAXL; l++) acc[l] = fmaf(s_aux[l * DD + k], g, acc[l]);
    }
    float w4j = w4[j], g3b = glu3_b[j];
    for (int l = 0; l < MAXL; l++) {
        float g3 = sigmoidf_(acc[l] + g3b + ueg);
        float tot = blockReduce128(g3 * w4j, s_rbuf);
        if (j == 0) s_beta[l] = tot * s_m[l];
    }
    __syncthreads();
    float su = 0.f;
    for (int l = 0; l < MAXL; l++) su = fmaf(s_beta[l], s_item[l * DD + j], su);

    float pa = sv * wc_w[j] + su * wc_w[DD + j];
    float asum = blockReduce128(pa, s_rbuf);
    if (j == 0) s_alpha = sigmoidf_(asum + wc_b[0]);
    __syncthreads();
    float alpha = s_alpha;
    float val = s_user[j] + alpha * sv + (1.0f - alpha) * su;
    __half hi = __float2half_rn(val);
    __half lo = __float2half_rn(val - __half2float(hi));
    g_seq_hi[(size_t)b * DD + j] = hi;
    g_seq_lo[(size_t)b * DD + j] = lo;
}

// ---------------- K5b: fp16 conversion for v2e ----------------
__global__ void k_split_v2e(const float* __restrict__ src, int n4) {
    int i = blockIdx.x * blockDim.x + threadIdx.x;
    if (i >= n4) return;
    float4 v = ((const float4*)src)[i];
    __half2* H = (__half2*)g_v2e_h;
    H[i * 2]     = __floats2half2_rn(v.x, v.y);
    H[i * 2 + 1] = __floats2half2_rn(v.z, v.w);
}

// ---------------- K6: HMMA fp16x2-split GEMM, 128x128 tile, 2 CTAs/SM -----
#define TM 128
#define TN 128
#define ASTR 136
#define ROWB (ASTR * 2)            // 272 bytes
#define TILEB (128 * ROWB)         // 34816
#define SA_HI 0
#define SA_LO TILEB
#define SB    (2 * TILEB)
#define SM_TOT (3 * TILEB)         // 104448

__global__ void __launch_bounds__(256, 2)
k_gemm_mma(float* __restrict__ out, int N, int Nout, int BS) {
    extern __shared__ char smem[];
    uint32_t sb = smem_u32(smem);
    int tid = threadIdx.x;
    int wid = tid >> 5, lane = tid & 31;
    int bn = blockIdx.x, bm = blockIdx.y;
    int rowBase = bm * TM;
    int colBase = bn * TN;

    {
        const uint4* aH = (const uint4*)g_seq_hi;
        const uint4* aL = (const uint4*)g_seq_lo;
        const uint4* bH = (const uint4*)g_v2e_h;
        uint4 z = make_uint4(0, 0, 0, 0);
        for (int i = tid; i < 128 * 16; i += 256) {
            int r = i >> 4, c = i & 15;
            uint32_t dst = (uint32_t)(r * ROWB + c * 16);
            int ga = rowBase + r;
            uint4 vh = z, vl = z;
            if (ga < BS) { vh = aH[ga * 16 + c]; vl = aL[ga * 16 + c]; }
            *(uint4*)(smem + SA_HI + dst) = vh;
            *(uint4*)(smem + SA_LO + dst) = vl;
            int gb = 1 + colBase + r;
            uint4 wh = z;
            if (gb < N) wh = bH[(size_t)gb * 16 + c];
            *(uint4*)(smem + SB + dst) = wh;
        }
    }
    __syncthreads();

    int warp_m = (wid >> 2) * 64;
    int warp_n = (wid & 3) * 32;

    int a_row = (lane & 7) + ((lane >> 3) & 1) * 8;
    int a_k8  = ((lane >> 4) & 1) * 8;
    int b_row = (lane & 7) + ((lane >> 4) & 1) * 8;
    int b_k8  = ((lane >> 3) & 1) * 8;

    float accm[4][4][4];
#pragma unroll
    for (int mi = 0; mi < 4; mi++)
#pragma unroll
        for (int nb = 0; nb < 4; nb++)
#pragma unroll
            for (int q = 0; q < 4; q++) accm[mi][nb][q] = 0.f;

#pragma unroll
    for (int ks = 0; ks < 8; ks++) {
        int kc = ks * 16;
        uint32_t bb[8];
        {
            uint32_t addr0 = sb + SB + (uint32_t)((warp_n + b_row) * ROWB +
                                                  (kc + b_k8) * 2);
            ldsm_x4(bb[0], bb[1], bb[2], bb[3], addr0);
            uint32_t addr1 = addr0 + 16 * ROWB;
            ldsm_x4(bb[4], bb[5], bb[6], bb[7], addr1);
        }
#pragma unroll
        for (int t = 0; t < 2; t++) {
            uint32_t aBase = sb + (t == 0 ? SA_HI : SA_LO);
#pragma unroll
            for (int mi = 0; mi < 4; mi++) {
                uint32_t a0, a1, a2, a3;
                uint32_t addr = aBase + (uint32_t)((warp_m + mi * 16 + a_row) * ROWB +
                                                   (kc + a_k8) * 2);
                ldsm_x4(a0, a1, a2, a3, addr);
                mma16816(accm[mi][0], a0, a1, a2, a3, bb[0], bb[1]);
                mma16816(accm[mi][1], a0, a1, a2, a3, bb[2], bb[3]);
                mma16816(accm[mi][2], a0, a1, a2, a3, bb[4], bb[5]);
                mma16816(accm[mi][3], a0, a1, a2, a3, bb[6], bb[7]);
            }
        }
    }

    int grp = lane >> 2;
    int lc2 = (lane & 3) * 2;
#pragma unroll
    for (int mi = 0; mi < 4; mi++) {
        int r0 = rowBase + warp_m + mi * 16 + grp;
        if (r0 >= BS) continue;
        size_t ro0 = (size_t)r0 * (size_t)Nout;
        size_t ro1 = (size_t)(r0 + 8) * (size_t)Nout;
#pragma unroll
        for (int nb = 0; nb < 4; nb++) {
            int col = colBase + warp_n + nb * 8 + lc2;
            if (col < Nout)     out[ro0 + col]     = accm[mi][nb][0];
            if (col + 1 < Nout) out[ro0 + col + 1] = accm[mi][nb][1];
            if (col < Nout)     out[ro1 + col]     = accm[mi][nb][2];
            if (col + 1 < Nout) out[ro1 + col + 1] = accm[mi][nb][3];
        }
    }
}

// ---------------- launch ----------------
extern "C" void kernel_launch(void* const* d_in, const int* in_sizes, int n_in,
                              void* d_out, int out_size) {
    const int* user     = (const int*)d_in[0];
    const int* seq      = (const int*)d_in[1];
    const int* mask     = (const int*)d_in[2];
    const int* pos_idx  = (const int*)d_in[4];
    const int* edge_src = (const int*)d_in[5];
    const int* edge_dst = (const int*)d_in[6];
    const int* item_num = (const int*)d_in[7];
    const float* v2e    = (const float*)d_in[8];
    const float* pos_w  = (const float*)d_in[9];
    const float* W_self = (const float*)d_in[10];
    const float* W_neigh= (const float*)d_in[11];
    const float* b_sage = (const float*)d_in[12];
    const float* w1     = (const float*)d_in[13];
    const float* w2     = (const float*)d_in[14];
    const float* glu1_w = (const float*)d_in[15];
    const float* glu1_b = (const float*)d_in[16];
    const float* glu2_w = (const float*)d_in[17];
    const float* w3     = (const float*)d_in[18];
    const float* w4     = (const float*)d_in[19];
    const float* glu3_w = (const float*)d_in[20];
    const float* glu3_b = (const float*)d_in[21];
    const float* glu4_w = (const float*)d_in[22];
    const float* wc_w   = (const float*)d_in[23];
    const float* wc_b   = (const float*)d_in[24];
    float* out = (float*)d_out;

    int BS = in_sizes[0];
    int L  = in_sizes[1] / BS;
    int E  = in_sizes[5];
    int N  = in_sizes[8] / DD;
    int Nout = N - 1;

    int tot = BS * L + BS;
    k_flags_zero<<<(tot * 32 + 255) / 256, 256>>>(seq, user, item_num, BS, L); // 0
    k_scatter_fused<<<(E + 255) / 256, 256>>>(edge_src, edge_dst, v2e, E);     // 1
    k_split_v2e<<<(N * DD / 4 + 255) / 256, 256>>>(v2e, N * DD / 4);           // 2
    int totalRows = BS * (L + 1);
    k_rows<<<(totalRows + RG - 1) / RG, 128>>>(v2e, W_self, W_neigh, b_sage,
                                               seq, user, item_num, L, totalRows); // 3
    k_attn<<<BS, 128>>>(pos_w, w1, w2, glu1_w, glu1_b, glu2_w, w3, w4,
                        glu3_w, glu3_b, glu4_w, wc_w, wc_b, mask, pos_idx, L); // 4
    cudaFuncSetAttribute(k_gemm_mma, cudaFuncAttributeMaxDynamicSharedMemorySize, SM_TOT);
    dim3 grid((Nout + TN - 1) / TN, (BS + TM - 1) / TM);
    k_gemm_mma<<<grid, 256, SM_TOT>>>(out, N, Nout, BS);                       // 5
}